// round 14
// baseline (speedup 1.0000x reference)
#include <cuda_runtime.h>
#include <cuda_fp16.h>
#include <cstdint>

#define N_HEAD 16
#define C_EMBD 1024
#define HD     64
#define BATCH  4
#define SEQ    2048
#define MTOT   (BATCH * SEQ)   // 8192

// ---------------- scratch (device globals: allocation-free) ----------------
__device__ __half g_Qh[BATCH * N_HEAD * SEQ * HD];     // Q fp16
__device__ __half g_Kh[BATCH * N_HEAD * SEQ * HD];     // K fp16
__device__ __half g_Vh[BATCH * N_HEAD * SEQ * HD];     // V fp16

__device__ __half g_Xh[MTOT * C_EMBD];                 // x as fp16
__device__ __half g_Yh[MTOT * C_EMBD];                 // attn output as fp16
__device__ __half g_Wa[3 * C_EMBD * C_EMBD];           // [N=3072][K=1024] fp16
__device__ __half g_Wp[C_EMBD * C_EMBD];               // [N=1024][K=1024] fp16

// ---------------- helpers ----------------
__device__ __forceinline__ uint32_t smem_u32(const void* p) {
    uint32_t a;
    asm("{ .reg .u64 t; cvta.to.shared.u64 t, %1; cvt.u32.u64 %0, t; }" : "=r"(a) : "l"(p));
    return a;
}

__device__ __forceinline__ void ldsm_x4(uint32_t& r0, uint32_t& r1,
                                        uint32_t& r2, uint32_t& r3, uint32_t addr) {
    asm volatile("ldmatrix.sync.aligned.m8n8.x4.shared.b16 {%0,%1,%2,%3}, [%4];"
                 : "=r"(r0), "=r"(r1), "=r"(r2), "=r"(r3) : "r"(addr));
}

__device__ __forceinline__ void ldsm_x4_t(uint32_t& r0, uint32_t& r1,
                                          uint32_t& r2, uint32_t& r3, uint32_t addr) {
    asm volatile("ldmatrix.sync.aligned.m8n8.x4.trans.shared.b16 {%0,%1,%2,%3}, [%4];"
                 : "=r"(r0), "=r"(r1), "=r"(r2), "=r"(r3) : "r"(addr));
}

__device__ __forceinline__ void mma_f16(float* c, const uint32_t* a, const uint32_t* b) {
    asm volatile(
        "mma.sync.aligned.m16n8k16.row.col.f32.f16.f16.f32 "
        "{%0,%1,%2,%3}, {%4,%5,%6,%7}, {%8,%9}, {%0,%1,%2,%3};"
        : "+f"(c[0]), "+f"(c[1]), "+f"(c[2]), "+f"(c[3])
        : "r"(a[0]), "r"(a[1]), "r"(a[2]), "r"(a[3]), "r"(b[0]), "r"(b[1]));
}

__device__ __forceinline__ void cp_async16(uint32_t dst, const void* src) {
    asm volatile("cp.async.cg.shared.global [%0], [%1], 16;" :: "r"(dst), "l"(src));
}
__device__ __forceinline__ void cp_commit() {
    asm volatile("cp.async.commit_group;");
}
template <int N>
__device__ __forceinline__ void cp_wait() {
    asm volatile("cp.async.wait_group %0;" :: "n"(N));
}

// ---------------- prep kernels ----------------
__global__ __launch_bounds__(256)
void tofp16_kernel(const float* __restrict__ X) {
    int i = blockIdx.x * 256 + threadIdx.x;           // float4 index
    float4 v = ((const float4*)X)[i];
    ((__half2*)g_Xh)[2*i+0] = __floats2half2_rn(v.x, v.y);
    ((__half2*)g_Xh)[2*i+1] = __floats2half2_rn(v.z, v.w);
}

// transpose:  W[K, N] fp32 -> Wt[N, K] fp16
__global__ __launch_bounds__(256)
void wt_kernel(const float* __restrict__ W, int which, int N) {
    __shared__ float t[32][33];
    __half* Dst = which ? g_Wp : g_Wa;
    const int K = C_EMBD;
    int n0 = blockIdx.x * 32, k0 = blockIdx.y * 32;
    int tx = threadIdx.x, ty = threadIdx.y;
#pragma unroll
    for (int s = 0; s < 4; s++) {
        int i = ty + 8 * s;
        t[i][tx] = W[(size_t)(k0 + i) * N + n0 + tx];
    }
    __syncthreads();
#pragma unroll
    for (int s = 0; s < 4; s++) {
        int i = ty + 8 * s;
        Dst[(size_t)(n0 + i) * K + k0 + tx] = __float2half_rn(t[tx][i]);
    }
}

// ---------------- HMMA GEMM (fp16 single pass) ----------------
// 256 threads, CTA tile 128(M)x64(N), BK=64, cp.async 3-stage, 2 CTAs/SM.
#define BKC     64
#define NCHUNK  (C_EMBD / BKC)          // 16
#define ROWB    144                      // smem row pitch bytes (128B data + 16 pad)
#define A_ROWS  128
#define B_ROWS  64
#define A_OFF   0
#define B_OFF   (A_ROWS * ROWB)          // 18432
#define STAGEB  ((A_ROWS + B_ROWS) * ROWB)  // 27648
#define NSTAGE  3
#define GEMM_SMEM_TOT (NSTAGE * STAGEB)  // 82944

template <int MODE>   // 0: QKV gemm (scatter Q/K/V fp16), 1: proj gemm (fp32 out)
__global__ __launch_bounds__(256, 2)
void mma_gemm(const float* __restrict__ bias, float* __restrict__ Cout, int N)
{
    extern __shared__ char smem[];

    const __half* Ain = (MODE == 0) ? g_Xh : g_Yh;
    const __half* Bw  = (MODE == 0) ? g_Wa : g_Wp;

    const int K = C_EMBD;
    int tid = threadIdx.x;
    int lane = tid & 31, wid = tid >> 5;
    int wm = wid & 3, wn = wid >> 2;                  // 4(M) x 2(N) warps, 32x32 each
    int bn = blockIdx.x * 64;
    int bm = blockIdx.y * 128;

    uint32_t sb = smem_u32(smem);

    // cp.async mapping:
    //  A: 128 rows x 8 slots(16B) = 1024 cps -> 4/thread: row=tid>>1, slot=(tid&1)*4+i
    //  B:  64 rows x 8 slots       =  512 cps -> 2/thread: row=tid>>2, slot=(tid&3)*2+j
    int ra_ld = tid >> 1;
    int ca_ld = (tid & 1) * 4;            // *16B
    int rb_ld = tid >> 2;
    int cb_ld = (tid & 3) * 2;            // *16B
    const __half* pA = Ain + (size_t)(bm + ra_ld) * K + ca_ld * 8;
    const __half* pB = Bw  + (size_t)(bn + rb_ld) * K + cb_ld * 8;
    uint32_t stA = (uint32_t)(ra_ld * ROWB + ca_ld * 16);
    uint32_t stB = (uint32_t)(rb_ld * ROWB + cb_ld * 16);

    uint32_t a_row = (uint32_t)(wm * 32 + (lane & 15));          // + mf*16
    uint32_t a_colb = (uint32_t)((lane >> 4) * 16);              // + ks*32
    int bq = lane >> 3;
    uint32_t b_row = (uint32_t)(wn * 32 + ((bq >> 1) << 3) + (lane & 7));  // + nb*16
    uint32_t b_colb = (uint32_t)((bq & 1) * 16);                           // + ks*32

    float acc[2][4][4];
#pragma unroll
    for (int i = 0; i < 2; i++)
#pragma unroll
        for (int j = 0; j < 4; j++)
#pragma unroll
            for (int k = 0; k < 4; k++) acc[i][j][k] = 0.0f;

    // prologue: stages 0,1
#pragma unroll
    for (int st = 0; st < 2; st++) {
        uint32_t d = sb + st * STAGEB;
        int k0 = st * BKC;
#pragma unroll
        for (int i = 0; i < 4; i++)
            cp_async16(d + A_OFF + stA + i * 16, pA + k0 + i * 8);
#pragma unroll
        for (int j = 0; j < 2; j++)
            cp_async16(d + B_OFF + stB + j * 16, pB + k0 + j * 8);
        cp_commit();
    }

    int stage_c = 0;
    int stage_l = 2;
    for (int ch = 0; ch < NCHUNK; ch++) {
        cp_wait<1>();
        __syncthreads();

        if (ch + 2 < NCHUNK) {
            uint32_t d = sb + stage_l * STAGEB;
            int k0 = (ch + 2) * BKC;
#pragma unroll
            for (int i = 0; i < 4; i++)
                cp_async16(d + A_OFF + stA + i * 16, pA + k0 + i * 8);
#pragma unroll
            for (int j = 0; j < 2; j++)
                cp_async16(d + B_OFF + stB + j * 16, pB + k0 + j * 8);
        }
        cp_commit();

        uint32_t stage = sb + stage_c * STAGEB;
#pragma unroll
        for (int ks = 0; ks < 4; ks++) {
            uint32_t kb = (uint32_t)(ks * 32);
            uint32_t a[2][4];
#pragma unroll
            for (int mf = 0; mf < 2; mf++) {
                uint32_t ra = stage + A_OFF + (a_row + mf * 16) * ROWB + a_colb + kb;
                ldsm_x4(a[mf][0], a[mf][1], a[mf][2], a[mf][3], ra);
            }
            uint32_t bh[4][2];
#pragma unroll
            for (int nb = 0; nb < 2; nb++) {
                uint32_t rb = stage + B_OFF + (b_row + nb * 16) * ROWB + b_colb + kb;
                ldsm_x4(bh[2*nb][0], bh[2*nb][1], bh[2*nb+1][0], bh[2*nb+1][1], rb);
            }
#pragma unroll
            for (int mf = 0; mf < 2; mf++)
#pragma unroll
                for (int nf = 0; nf < 4; nf++)
                    mma_f16(acc[mf][nf], a[mf], bh[nf]);
        }

        stage_c = (stage_c == NSTAGE - 1) ? 0 : stage_c + 1;
        stage_l = (stage_l == NSTAGE - 1) ? 0 : stage_l + 1;
    }

    // epilogue: bias + write
#pragma unroll
    for (int mf = 0; mf < 2; mf++) {
#pragma unroll
        for (int nf = 0; nf < 4; nf++) {
            int m0 = bm + wm * 32 + mf * 16 + (lane >> 2);
            int n0 = bn + wn * 32 + nf * 8 + 2 * (lane & 3);
#pragma unroll
            for (int half = 0; half < 2; half++) {
                int m = m0 + half * 8;
                float v0 = acc[mf][nf][2 * half + 0] + bias[n0];
                float v1 = acc[mf][nf][2 * half + 1] + bias[n0 + 1];
                if (MODE == 0) {
                    int bb = m >> 11, t = m & 2047;
                    int which = n0 >> 10;
                    int cc = n0 & 1023;
                    int h = cc >> 6, d = cc & 63;
                    __half* Dst = (which == 0) ? g_Qh : (which == 1) ? g_Kh : g_Vh;
                    size_t idx = ((((size_t)bb * N_HEAD) + h) * SEQ + t) * HD + d;
                    *(__half2*)&Dst[idx] = __floats2half2_rn(v0, v1);
                } else {
                    *(float2*)&Cout[(size_t)m * N + n0] = make_float2(v0, v1);
                }
            }
        }
    }
}

// ---------------------------------------------------------------------------
// HMMA flash attention: CTA = (b*h, 64-query block), 4 warps x 16 rows.
// 2-pass: S = Q*K, PV = P*V. Softmax in registers.
// ---------------------------------------------------------------------------
#define FPITCH 144    // smem row pitch (bytes)
#define FTILE  (64 * FPITCH)   // 9216 B

__global__ __launch_bounds__(128)
void flash_mma_kernel()
{
    extern __shared__ char fsm[];
    char* pQ = fsm;
    char* pK = fsm + 1 * FTILE;
    char* pV = fsm + 2 * FTILE;
    const uint32_t Qs = smem_u32(pQ);
    const uint32_t Ks = smem_u32(pK);
    const uint32_t Vs = smem_u32(pV);

    int tid = threadIdx.x, lane = tid & 31, w = tid >> 5;
    int qb = (int)(gridDim.x - 1) - (int)blockIdx.x;    // heavy blocks first
    int bh = blockIdx.y;
    int q0 = qb * 64;
    size_t base = (size_t)bh * SEQ * HD;

    // load Q tile
    {
        int r = tid >> 3, s = tid & 7;
#pragma unroll
        for (int it = 0; it < 4; it++) {
            int rr = r + it * 16;
            size_t off = base + (size_t)(q0 + rr) * HD + s * 8;
            *(uint4*)(pQ + rr * FPITCH + s * 16) = *(const uint4*)(g_Qh + off);
        }
    }

    float m0 = -1e30f, m1 = -1e30f, l0 = 0.0f, l1 = 0.0f;
    float O[8][4];
#pragma unroll
    for (int i = 0; i < 8; i++)
#pragma unroll
        for (int j = 0; j < 4; j++) O[i][j] = 0.0f;

    for (int kb = 0; kb <= qb; kb++) {
        __syncthreads();
        int k0 = kb * 64;
        {
            int r = tid >> 3, s = tid & 7;
#pragma unroll
            for (int it = 0; it < 4; it++) {
                int rr = r + it * 16;
                size_t off = base + (size_t)(k0 + rr) * HD + s * 8;
                *(uint4*)(pK + rr * FPITCH + s * 16) = *(const uint4*)(g_Kh + off);
                *(uint4*)(pV + rr * FPITCH + s * 16) = *(const uint4*)(g_Vh + off);
            }
        }
        __syncthreads();

        // ---- S = Q K^T ----
        float S[8][4];
#pragma unroll
        for (int i = 0; i < 8; i++)
#pragma unroll
            for (int j = 0; j < 4; j++) S[i][j] = 0.0f;

        int bq = lane >> 3;
#pragma unroll
        for (int s = 0; s < 4; s++) {
            uint32_t a[4];
            uint32_t ra = Qs + (w * 16 + (lane & 15)) * FPITCH + (lane >> 4) * 16 + s * 32;
            ldsm_x4(a[0], a[1], a[2], a[3], ra);
            uint32_t bh_[4][4];
#pragma unroll
            for (int nt = 0; nt < 4; nt++) {
                uint32_t rb = Ks + (nt * 16 + ((bq >> 1) << 3) + (lane & 7)) * FPITCH
                            + (bq & 1) * 16 + s * 32;
                ldsm_x4(bh_[nt][0], bh_[nt][1], bh_[nt][2], bh_[nt][3], rb);
            }
#pragma unroll
            for (int nt = 0; nt < 4; nt++) {
                mma_f16(S[2*nt],   a, &bh_[nt][0]);
                mma_f16(S[2*nt+1], a, &bh_[nt][2]);
            }
        }

        // ---- scale + causal mask ----
#pragma unroll
        for (int nb = 0; nb < 8; nb++)
#pragma unroll
            for (int e = 0; e < 4; e++) S[nb][e] *= 0.125f;

        if (kb == qb) {
            int rl0 = w * 16 + (lane >> 2);
#pragma unroll
            for (int nb = 0; nb < 8; nb++) {
                int c = nb * 8 + 2 * (lane & 3);
                if (c     > rl0)     S[nb][0] = -1e30f;
                if (c + 1 > rl0)     S[nb][1] = -1e30f;
                if (c     > rl0 + 8) S[nb][2] = -1e30f;
                if (c + 1 > rl0 + 8) S[nb][3] = -1e30f;
            }
        }

        // ---- online softmax ----
        float mx0 = -1e30f, mx1 = -1e30f;
#pragma unroll
        for (int nb = 0; nb < 8; nb++) {
            mx0 = fmaxf(mx0, fmaxf(S[nb][0], S[nb][1]));
            mx1 = fmaxf(mx1, fmaxf(S[nb][2], S[nb][3]));
        }
        mx0 = fmaxf(mx0, __shfl_xor_sync(0xffffffffu, mx0, 1));
        mx0 = fmaxf(mx0, __shfl_xor_sync(0xffffffffu, mx0, 2));
        mx1 = fmaxf(mx1, __shfl_xor_sync(0xffffffffu, mx1, 1));
        mx1 = fmaxf(mx1, __shfl_xor_sync(0xffffffffu, mx1, 2));
        float mn0 = fmaxf(m0, mx0), mn1 = fmaxf(m1, mx1);
        float corr0 = __expf(m0 - mn0), corr1 = __expf(m1 - mn1);
        float s0 = 0.0f, s1 = 0.0f;
#pragma unroll
        for (int nb = 0; nb < 8; nb++) {
            S[nb][0] = __expf(S[nb][0] - mn0); s0 += S[nb][0];
            S[nb][1] = __expf(S[nb][1] - mn0); s0 += S[nb][1];
            S[nb][2] = __expf(S[nb][2] - mn1); s1 += S[nb][2];
            S[nb][3] = __expf(S[nb][3] - mn1); s1 += S[nb][3];
        }
        s0 += __shfl_xor_sync(0xffffffffu, s0, 1);
        s0 += __shfl_xor_sync(0xffffffffu, s0, 2);
        s1 += __shfl_xor_sync(0xffffffffu, s1, 1);
        s1 += __shfl_xor_sync(0xffffffffu, s1, 2);
        l0 = l0 * corr0 + s0;
        l1 = l1 * corr1 + s1;
        m0 = mn0; m1 = mn1;
#pragma unroll
        for (int nb = 0; nb < 8; nb++) {
            O[nb][0] *= corr0; O[nb][1] *= corr0;
            O[nb][2] *= corr1; O[nb][3] *= corr1;
        }

        // ---- O += P V ----
#pragma unroll
        for (int s = 0; s < 4; s++) {
            uint32_t pa[4];
            __half2 p0 = __floats2half2_rn(S[2*s][0],   S[2*s][1]);
            __half2 p1 = __floats2half2_rn(S[2*s][2],   S[2*s][3]);
            __half2 p2 = __floats2half2_rn(S[2*s+1][0], S[2*s+1][1]);
            __half2 p3 = __floats2half2_rn(S[2*s+1][2], S[2*s+1][3]);
            pa[0] = *(uint32_t*)&p0;
            pa[1] = *(uint32_t*)&p1;
            pa[2] = *(uint32_t*)&p2;
            pa[3] = *(uint32_t*)&p3;
            uint32_t vh[4][4];
#pragma unroll
            for (int nt = 0; nt < 4; nt++) {
                uint32_t rv = Vs + (s * 16 + (lane & 7) + ((lane >> 3) & 1) * 8) * FPITCH
                            + nt * 32 + (lane >> 4) * 16;
                ldsm_x4_t(vh[nt][0], vh[nt][1], vh[nt][2], vh[nt][3], rv);
            }
#pragma unroll
            for (int nt = 0; nt < 4; nt++) {
                mma_f16(O[2*nt],   pa, &vh[nt][0]);
                mma_f16(O[2*nt+1], pa, &vh[nt][2]);
            }
        }
    }

    // ---- normalize + write Y (fp16, [B,T,C]) ----
    int b = bh >> 4, h = bh & 15;
    int r0g = q0 + w * 16 + (lane >> 2);
    int dcol = 2 * (lane & 3);
    float inv0 = 1.0f / l0, inv1 = 1.0f / l1;
#pragma unroll
    for (int nb = 0; nb < 8; nb++) {
        int d = nb * 8 + dcol;
        {
            size_t idx = ((size_t)(b * SEQ + r0g)) * C_EMBD + h * HD + d;
            *(__half2*)&g_Yh[idx] = __floats2half2_rn(O[nb][0] * inv0, O[nb][1] * inv0);
        }
        {
            size_t idx = ((size_t)(b * SEQ + r0g + 8)) * C_EMBD + h * HD + d;
            *(__half2*)&g_Yh[idx] = __floats2half2_rn(O[nb][2] * inv1, O[nb][3] * inv1);
        }
    }
}

// ---------------------------------------------------------------------------
extern "C" void kernel_launch(void* const* d_in, const int* in_sizes, int n_in,
                              void* d_out, int out_size)
{
    const float* x      = (const float*)d_in[0];
    const float* W_attn = (const float*)d_in[1];
    const float* b_attn = (const float*)d_in[2];
    const float* W_proj = (const float*)d_in[3];
    const float* b_proj = (const float*)d_in[4];
    float* out = (float*)d_out;

    (void)in_sizes; (void)n_in; (void)out_size;

    static const int FLASH_SMEM = 3 * FTILE;                        // 27648 B
    cudaFuncSetAttribute(flash_mma_kernel,
                         cudaFuncAttributeMaxDynamicSharedMemorySize, FLASH_SMEM);
    cudaFuncSetAttribute(mma_gemm<0>,
                         cudaFuncAttributeMaxDynamicSharedMemorySize, GEMM_SMEM_TOT);
    cudaFuncSetAttribute(mma_gemm<1>,
                         cudaFuncAttributeMaxDynamicSharedMemorySize, GEMM_SMEM_TOT);

    // 0) prep: x -> fp16; transpose weights -> fp16
    tofp16_kernel<<<MTOT * C_EMBD / 4 / 256, 256>>>(x);
    wt_kernel<<<dim3(3 * C_EMBD / 32, C_EMBD / 32), dim3(32, 8)>>>(W_attn, 0, 3 * C_EMBD);
    wt_kernel<<<dim3(C_EMBD / 32, C_EMBD / 32), dim3(32, 8)>>>(W_proj, 1, C_EMBD);

    // 1) QKV GEMM (fp16, 128x64 tiles, 2 CTAs/SM) -> Q/K/V fp16 [B,H,T,hd]
    mma_gemm<0><<<dim3(3 * C_EMBD / 64, MTOT / 128), 256, GEMM_SMEM_TOT>>>(
        b_attn, nullptr, 3 * C_EMBD);

    // 2) causal flash attention (fp16 2-pass) -> Y fp16
    flash_mma_kernel<<<dim3(SEQ / 64, BATCH * N_HEAD), 128, FLASH_SMEM>>>();

    // 3) output projection (fp16, 128x64 tiles) + bias -> d_out
    mma_gemm<1><<<dim3(C_EMBD / 64, MTOT / 128), 256, GEMM_SMEM_TOT>>>(
        b_proj, out, C_EMBD);
}

// round 16
// speedup vs baseline: 1.0943x; 1.0943x over previous
#include <cuda_runtime.h>
#include <cuda_fp16.h>
#include <cstdint>

#define N_HEAD 16
#define C_EMBD 1024
#define HD     64
#define BATCH  4
#define SEQ    2048
#define MTOT   (BATCH * SEQ)   // 8192

// ---------------- scratch (device globals: allocation-free) ----------------
__device__ __half g_Qh[BATCH * N_HEAD * SEQ * HD];     // Q fp16
__device__ __half g_Kh[BATCH * N_HEAD * SEQ * HD];     // K fp16
__device__ __half g_Vh[BATCH * N_HEAD * SEQ * HD];     // V fp16

__device__ __half g_Xh[MTOT * C_EMBD];                 // x as fp16
__device__ __half g_Yh[MTOT * C_EMBD];                 // attn output as fp16
__device__ __half g_Wa[3 * C_EMBD * C_EMBD];           // [N=3072][K=1024] fp16
__device__ __half g_Wp[C_EMBD * C_EMBD];               // [N=1024][K=1024] fp16

// ---------------- helpers ----------------
__device__ __forceinline__ uint32_t smem_u32(const void* p) {
    uint32_t a;
    asm("{ .reg .u64 t; cvta.to.shared.u64 t, %1; cvt.u32.u64 %0, t; }" : "=r"(a) : "l"(p));
    return a;
}

__device__ __forceinline__ void ldsm_x4(uint32_t& r0, uint32_t& r1,
                                        uint32_t& r2, uint32_t& r3, uint32_t addr) {
    asm volatile("ldmatrix.sync.aligned.m8n8.x4.shared.b16 {%0,%1,%2,%3}, [%4];"
                 : "=r"(r0), "=r"(r1), "=r"(r2), "=r"(r3) : "r"(addr));
}

__device__ __forceinline__ void ldsm_x4_t(uint32_t& r0, uint32_t& r1,
                                          uint32_t& r2, uint32_t& r3, uint32_t addr) {
    asm volatile("ldmatrix.sync.aligned.m8n8.x4.trans.shared.b16 {%0,%1,%2,%3}, [%4];"
                 : "=r"(r0), "=r"(r1), "=r"(r2), "=r"(r3) : "r"(addr));
}

__device__ __forceinline__ void mma_f16(float* c, const uint32_t* a, const uint32_t* b) {
    asm volatile(
        "mma.sync.aligned.m16n8k16.row.col.f32.f16.f16.f32 "
        "{%0,%1,%2,%3}, {%4,%5,%6,%7}, {%8,%9}, {%0,%1,%2,%3};"
        : "+f"(c[0]), "+f"(c[1]), "+f"(c[2]), "+f"(c[3])
        : "r"(a[0]), "r"(a[1]), "r"(a[2]), "r"(a[3]), "r"(b[0]), "r"(b[1]));
}

__device__ __forceinline__ void cp_async16(uint32_t dst, const void* src) {
    asm volatile("cp.async.cg.shared.global [%0], [%1], 16;" :: "r"(dst), "l"(src));
}
__device__ __forceinline__ void cp_commit() {
    asm volatile("cp.async.commit_group;");
}
template <int N>
__device__ __forceinline__ void cp_wait() {
    asm volatile("cp.async.wait_group %0;" :: "n"(N));
}

// ---------------- prep kernels ----------------
__global__ __launch_bounds__(256)
void tofp16_kernel(const float* __restrict__ X) {
    int i = blockIdx.x * 256 + threadIdx.x;           // float4 index
    float4 v = ((const float4*)X)[i];
    ((__half2*)g_Xh)[2*i+0] = __floats2half2_rn(v.x, v.y);
    ((__half2*)g_Xh)[2*i+1] = __floats2half2_rn(v.z, v.w);
}

// transpose:  W[K, N] fp32 -> Wt[N, K] fp16
__global__ __launch_bounds__(256)
void wt_kernel(const float* __restrict__ W, int which, int N) {
    __shared__ float t[32][33];
    __half* Dst = which ? g_Wp : g_Wa;
    const int K = C_EMBD;
    int n0 = blockIdx.x * 32, k0 = blockIdx.y * 32;
    int tx = threadIdx.x, ty = threadIdx.y;
#pragma unroll
    for (int s = 0; s < 4; s++) {
        int i = ty + 8 * s;
        t[i][tx] = W[(size_t)(k0 + i) * N + n0 + tx];
    }
    __syncthreads();
#pragma unroll
    for (int s = 0; s < 4; s++) {
        int i = ty + 8 * s;
        Dst[(size_t)(n0 + i) * K + k0 + tx] = __float2half_rn(t[tx][i]);
    }
}

// ---------------- HMMA GEMM (fp16 single pass) ----------------
// 512 threads, CTA tile 128(M)x256(N), warp tile 32x64 (4Mx4N warps),
// BK=64, cp.async 3-stage.
#define BKC     64
#define NCHUNK  (C_EMBD / BKC)          // 16
#define ROWB    144                      // smem row pitch bytes (128B data + 16 pad)
#define A_ROWS  128
#define B_ROWS  256
#define A_OFF   0
#define B_OFF   (A_ROWS * ROWB)          // 18432
#define STAGEB  ((A_ROWS + B_ROWS) * ROWB)  // 55296
#define NSTAGE  3
#define GEMM_SMEM_TOT (NSTAGE * STAGEB)  // 165888

template <int MODE>   // 0: QKV gemm (scatter Q/K/V fp16), 1: proj gemm (fp32 out)
__global__ __launch_bounds__(512, 1)
void mma_gemm(const float* __restrict__ bias, float* __restrict__ Cout, int N)
{
    extern __shared__ char smem[];

    const __half* Ain = (MODE == 0) ? g_Xh : g_Yh;
    const __half* Bw  = (MODE == 0) ? g_Wa : g_Wp;

    const int K = C_EMBD;
    int tid = threadIdx.x;
    int lane = tid & 31, wid = tid >> 5;
    int wm = wid & 3, wn = wid >> 2;                  // 4(M) x 4(N) warps, 32x64 each
    int bn = blockIdx.x * 256;
    int bm = blockIdx.y * 128;

    uint32_t sb = smem_u32(smem);

    // cp.async mapping (per stage: A 1024 cps, B 2048 cps; 6 per thread)
    int ra_ld = tid >> 2;                 // 0..127
    int ca_ld = (tid & 3) * 2;            // slots (16B), 2 per thread
    int rb_ld = tid >> 1;                 // 0..255
    int cb_ld = (tid & 1) * 4;            // slots, 4 per thread
    const __half* pA = Ain + (size_t)(bm + ra_ld) * K + ca_ld * 8;
    const __half* pB = Bw  + (size_t)(bn + rb_ld) * K + cb_ld * 8;
    uint32_t stA = (uint32_t)(ra_ld * ROWB + ca_ld * 16);
    uint32_t stB = (uint32_t)(rb_ld * ROWB + cb_ld * 16);

    uint32_t a_row = (uint32_t)(wm * 32 + (lane & 15));          // + mf*16
    uint32_t a_colb = (uint32_t)((lane >> 4) * 16);              // + ks*32
    int bq = lane >> 3;
    uint32_t b_row = (uint32_t)(wn * 64 + ((bq >> 1) << 3) + (lane & 7));  // + nb*16
    uint32_t b_colb = (uint32_t)((bq & 1) * 16);                           // + ks*32

    float acc[2][8][4];
#pragma unroll
    for (int i = 0; i < 2; i++)
#pragma unroll
        for (int j = 0; j < 8; j++)
#pragma unroll
            for (int k = 0; k < 4; k++) acc[i][j][k] = 0.0f;

    // prologue: stages 0,1
#pragma unroll
    for (int st = 0; st < 2; st++) {
        uint32_t d = sb + st * STAGEB;
        int k0 = st * BKC;
#pragma unroll
        for (int i = 0; i < 2; i++)
            cp_async16(d + A_OFF + stA + i * 16, pA + k0 + i * 8);
#pragma unroll
        for (int j = 0; j < 4; j++)
            cp_async16(d + B_OFF + stB + j * 16, pB + k0 + j * 8);
        cp_commit();
    }

    int stage_c = 0;
    int stage_l = 2;
    for (int ch = 0; ch < NCHUNK; ch++) {
        cp_wait<1>();
        __syncthreads();

        if (ch + 2 < NCHUNK) {
            uint32_t d = sb + stage_l * STAGEB;
            int k0 = (ch + 2) * BKC;
#pragma unroll
            for (int i = 0; i < 2; i++)
                cp_async16(d + A_OFF + stA + i * 16, pA + k0 + i * 8);
#pragma unroll
            for (int j = 0; j < 4; j++)
                cp_async16(d + B_OFF + stB + j * 16, pB + k0 + j * 8);
        }
        cp_commit();

        uint32_t stage = sb + stage_c * STAGEB;
#pragma unroll
        for (int ks = 0; ks < 4; ks++) {
            uint32_t kb = (uint32_t)(ks * 32);
            uint32_t a[2][4];
#pragma unroll
            for (int mf = 0; mf < 2; mf++) {
                uint32_t ra = stage + A_OFF + (a_row + mf * 16) * ROWB + a_colb + kb;
                ldsm_x4(a[mf][0], a[mf][1], a[mf][2], a[mf][3], ra);
            }
            uint32_t bh[8][2];
#pragma unroll
            for (int nb = 0; nb < 4; nb++) {
                uint32_t rb = stage + B_OFF + (b_row + nb * 16) * ROWB + b_colb + kb;
                ldsm_x4(bh[2*nb][0], bh[2*nb][1], bh[2*nb+1][0], bh[2*nb+1][1], rb);
            }
#pragma unroll
            for (int mf = 0; mf < 2; mf++)
#pragma unroll
                for (int nf = 0; nf < 8; nf++)
                    mma_f16(acc[mf][nf], a[mf], bh[nf]);
        }

        stage_c = (stage_c == NSTAGE - 1) ? 0 : stage_c + 1;
        stage_l = (stage_l == NSTAGE - 1) ? 0 : stage_l + 1;
    }

    // epilogue: bias + write
#pragma unroll
    for (int mf = 0; mf < 2; mf++) {
#pragma unroll
        for (int nf = 0; nf < 8; nf++) {
            int m0 = bm + wm * 32 + mf * 16 + (lane >> 2);
            int n0 = bn + wn * 64 + nf * 8 + 2 * (lane & 3);
#pragma unroll
            for (int half = 0; half < 2; half++) {
                int m = m0 + half * 8;
                float v0 = acc[mf][nf][2 * half + 0] + bias[n0];
                float v1 = acc[mf][nf][2 * half + 1] + bias[n0 + 1];
                if (MODE == 0) {
                    int bb = m >> 11, t = m & 2047;
                    int which = n0 >> 10;
                    int cc = n0 & 1023;
                    int h = cc >> 6, d = cc & 63;
                    __half* Dst = (which == 0) ? g_Qh : (which == 1) ? g_Kh : g_Vh;
                    size_t idx = ((((size_t)bb * N_HEAD) + h) * SEQ + t) * HD + d;
                    *(__half2*)&Dst[idx] = __floats2half2_rn(v0, v1);
                } else {
                    *(float2*)&Cout[(size_t)m * N + n0] = make_float2(v0, v1);
                }
            }
        }
    }
}

// ---------------------------------------------------------------------------
// HMMA flash attention: CTA = (b*h, 64-query block), 4 warps x 16 rows.
// 2-pass: S = Q*K, PV = P*V. Softmax in registers.  (unchanged from R13)
// ---------------------------------------------------------------------------
#define FPITCH 144    // smem row pitch (bytes)
#define FTILE  (64 * FPITCH)   // 9216 B

__global__ __launch_bounds__(128)
void flash_mma_kernel()
{
    extern __shared__ char fsm[];
    char* pQ = fsm;
    char* pK = fsm + 1 * FTILE;
    char* pV = fsm + 2 * FTILE;
    const uint32_t Qs = smem_u32(pQ);
    const uint32_t Ks = smem_u32(pK);
    const uint32_t Vs = smem_u32(pV);

    int tid = threadIdx.x, lane = tid & 31, w = tid >> 5;
    int qb = (int)(gridDim.x - 1) - (int)blockIdx.x;    // heavy blocks first
    int bh = blockIdx.y;
    int q0 = qb * 64;
    size_t base = (size_t)bh * SEQ * HD;

    // load Q tile
    {
        int r = tid >> 3, s = tid & 7;
#pragma unroll
        for (int it = 0; it < 4; it++) {
            int rr = r + it * 16;
            size_t off = base + (size_t)(q0 + rr) * HD + s * 8;
            *(uint4*)(pQ + rr * FPITCH + s * 16) = *(const uint4*)(g_Qh + off);
        }
    }

    float m0 = -1e30f, m1 = -1e30f, l0 = 0.0f, l1 = 0.0f;
    float O[8][4];
#pragma unroll
    for (int i = 0; i < 8; i++)
#pragma unroll
        for (int j = 0; j < 4; j++) O[i][j] = 0.0f;

    for (int kb = 0; kb <= qb; kb++) {
        __syncthreads();
        int k0 = kb * 64;
        {
            int r = tid >> 3, s = tid & 7;
#pragma unroll
            for (int it = 0; it < 4; it++) {
                int rr = r + it * 16;
                size_t off = base + (size_t)(k0 + rr) * HD + s * 8;
                *(uint4*)(pK + rr * FPITCH + s * 16) = *(const uint4*)(g_Kh + off);
                *(uint4*)(pV + rr * FPITCH + s * 16) = *(const uint4*)(g_Vh + off);
            }
        }
        __syncthreads();

        // ---- S = Q K^T ----
        float S[8][4];
#pragma unroll
        for (int i = 0; i < 8; i++)
#pragma unroll
            for (int j = 0; j < 4; j++) S[i][j] = 0.0f;

        int bq = lane >> 3;
#pragma unroll
        for (int s = 0; s < 4; s++) {
            uint32_t a[4];
            uint32_t ra = Qs + (w * 16 + (lane & 15)) * FPITCH + (lane >> 4) * 16 + s * 32;
            ldsm_x4(a[0], a[1], a[2], a[3], ra);
            uint32_t bh_[4][4];
#pragma unroll
            for (int nt = 0; nt < 4; nt++) {
                uint32_t rb = Ks + (nt * 16 + ((bq >> 1) << 3) + (lane & 7)) * FPITCH
                            + (bq & 1) * 16 + s * 32;
                ldsm_x4(bh_[nt][0], bh_[nt][1], bh_[nt][2], bh_[nt][3], rb);
            }
#pragma unroll
            for (int nt = 0; nt < 4; nt++) {
                mma_f16(S[2*nt],   a, &bh_[nt][0]);
                mma_f16(S[2*nt+1], a, &bh_[nt][2]);
            }
        }

        // ---- scale + causal mask ----
#pragma unroll
        for (int nb = 0; nb < 8; nb++)
#pragma unroll
            for (int e = 0; e < 4; e++) S[nb][e] *= 0.125f;

        if (kb == qb) {
            int rl0 = w * 16 + (lane >> 2);
#pragma unroll
            for (int nb = 0; nb < 8; nb++) {
                int c = nb * 8 + 2 * (lane & 3);
                if (c     > rl0)     S[nb][0] = -1e30f;
                if (c + 1 > rl0)     S[nb][1] = -1e30f;
                if (c     > rl0 + 8) S[nb][2] = -1e30f;
                if (c + 1 > rl0 + 8) S[nb][3] = -1e30f;
            }
        }

        // ---- online softmax ----
        float mx0 = -1e30f, mx1 = -1e30f;
#pragma unroll
        for (int nb = 0; nb < 8; nb++) {
            mx0 = fmaxf(mx0, fmaxf(S[nb][0], S[nb][1]));
            mx1 = fmaxf(mx1, fmaxf(S[nb][2], S[nb][3]));
        }
        mx0 = fmaxf(mx0, __shfl_xor_sync(0xffffffffu, mx0, 1));
        mx0 = fmaxf(mx0, __shfl_xor_sync(0xffffffffu, mx0, 2));
        mx1 = fmaxf(mx1, __shfl_xor_sync(0xffffffffu, mx1, 1));
        mx1 = fmaxf(mx1, __shfl_xor_sync(0xffffffffu, mx1, 2));
        float mn0 = fmaxf(m0, mx0), mn1 = fmaxf(m1, mx1);
        float corr0 = __expf(m0 - mn0), corr1 = __expf(m1 - mn1);
        float s0 = 0.0f, s1 = 0.0f;
#pragma unroll
        for (int nb = 0; nb < 8; nb++) {
            S[nb][0] = __expf(S[nb][0] - mn0); s0 += S[nb][0];
            S[nb][1] = __expf(S[nb][1] - mn0); s0 += S[nb][1];
            S[nb][2] = __expf(S[nb][2] - mn1); s1 += S[nb][2];
            S[nb][3] = __expf(S[nb][3] - mn1); s1 += S[nb][3];
        }
        s0 += __shfl_xor_sync(0xffffffffu, s0, 1);
        s0 += __shfl_xor_sync(0xffffffffu, s0, 2);
        s1 += __shfl_xor_sync(0xffffffffu, s1, 1);
        s1 += __shfl_xor_sync(0xffffffffu, s1, 2);
        l0 = l0 * corr0 + s0;
        l1 = l1 * corr1 + s1;
        m0 = mn0; m1 = mn1;
#pragma unroll
        for (int nb = 0; nb < 8; nb++) {
            O[nb][0] *= corr0; O[nb][1] *= corr0;
            O[nb][2] *= corr1; O[nb][3] *= corr1;
        }

        // ---- O += P V ----
#pragma unroll
        for (int s = 0; s < 4; s++) {
            uint32_t pa[4];
            __half2 p0 = __floats2half2_rn(S[2*s][0],   S[2*s][1]);
            __half2 p1 = __floats2half2_rn(S[2*s][2],   S[2*s][3]);
            __half2 p2 = __floats2half2_rn(S[2*s+1][0], S[2*s+1][1]);
            __half2 p3 = __floats2half2_rn(S[2*s+1][2], S[2*s+1][3]);
            pa[0] = *(uint32_t*)&p0;
            pa[1] = *(uint32_t*)&p1;
            pa[2] = *(uint32_t*)&p2;
            pa[3] = *(uint32_t*)&p3;
            uint32_t vh[4][4];
#pragma unroll
            for (int nt = 0; nt < 4; nt++) {
                uint32_t rv = Vs + (s * 16 + (lane & 7) + ((lane >> 3) & 1) * 8) * FPITCH
                            + nt * 32 + (lane >> 4) * 16;
                ldsm_x4_t(vh[nt][0], vh[nt][1], vh[nt][2], vh[nt][3], rv);
            }
#pragma unroll
            for (int nt = 0; nt < 4; nt++) {
                mma_f16(O[2*nt],   pa, &vh[nt][0]);
                mma_f16(O[2*nt+1], pa, &vh[nt][2]);
            }
        }
    }

    // ---- normalize + write Y (fp16, [B,T,C]) ----
    int b = bh >> 4, h = bh & 15;
    int r0g = q0 + w * 16 + (lane >> 2);
    int dcol = 2 * (lane & 3);
    float inv0 = 1.0f / l0, inv1 = 1.0f / l1;
#pragma unroll
    for (int nb = 0; nb < 8; nb++) {
        int d = nb * 8 + dcol;
        {
            size_t idx = ((size_t)(b * SEQ + r0g)) * C_EMBD + h * HD + d;
            *(__half2*)&g_Yh[idx] = __floats2half2_rn(O[nb][0] * inv0, O[nb][1] * inv0);
        }
        {
            size_t idx = ((size_t)(b * SEQ + r0g + 8)) * C_EMBD + h * HD + d;
            *(__half2*)&g_Yh[idx] = __floats2half2_rn(O[nb][2] * inv1, O[nb][3] * inv1);
        }
    }
}

// ---------------------------------------------------------------------------
extern "C" void kernel_launch(void* const* d_in, const int* in_sizes, int n_in,
                              void* d_out, int out_size)
{
    const float* x      = (const float*)d_in[0];
    const float* W_attn = (const float*)d_in[1];
    const float* b_attn = (const float*)d_in[2];
    const float* W_proj = (const float*)d_in[3];
    const float* b_proj = (const float*)d_in[4];
    float* out = (float*)d_out;

    (void)in_sizes; (void)n_in; (void)out_size;

    static const int FLASH_SMEM = 3 * FTILE;                        // 27648 B
    cudaFuncSetAttribute(flash_mma_kernel,
                         cudaFuncAttributeMaxDynamicSharedMemorySize, FLASH_SMEM);
    cudaFuncSetAttribute(mma_gemm<0>,
                         cudaFuncAttributeMaxDynamicSharedMemorySize, GEMM_SMEM_TOT);
    cudaFuncSetAttribute(mma_gemm<1>,
                         cudaFuncAttributeMaxDynamicSharedMemorySize, GEMM_SMEM_TOT);

    // 0) prep: x -> fp16; transpose weights -> fp16
    tofp16_kernel<<<MTOT * C_EMBD / 4 / 256, 256>>>(x);
    wt_kernel<<<dim3(3 * C_EMBD / 32, C_EMBD / 32), dim3(32, 8)>>>(W_attn, 0, 3 * C_EMBD);
    wt_kernel<<<dim3(C_EMBD / 32, C_EMBD / 32), dim3(32, 8)>>>(W_proj, 1, C_EMBD);

    // 1) QKV GEMM (fp16, 128x256 tiles) -> Q/K/V fp16 [B,H,T,hd]
    mma_gemm<0><<<dim3(3 * C_EMBD / 256, MTOT / 128), 512, GEMM_SMEM_TOT>>>(
        b_attn, nullptr, 3 * C_EMBD);

    // 2) causal flash attention (fp16 2-pass) -> Y fp16
    flash_mma_kernel<<<dim3(SEQ / 64, BATCH * N_HEAD), 128, FLASH_SMEM>>>();

    // 3) output projection (fp16, 128x256 tiles) + bias -> d_out
    mma_gemm<1><<<dim3(C_EMBD / 256, MTOT / 128), 512, GEMM_SMEM_TOT>>>(
        b_proj, out, C_EMBD);
}